// round 15
// baseline (speedup 1.0000x reference)
#include <cuda_runtime.h>
#include <math.h>

#define V_   100000
#define D_   128
#define B_   4096
#define NEG_ 5
#define DI_  170
#define DIP_ 176
#define BT_  32
#define NBLK (B_ / BT_)      // 128
#define THREADS 1024
#define SQRTD 11.3137084989847604f

#define NW2  348             // whg2 row stride (float2 units)
#define ES2  36              // emb2 / a_t2 row stride (float2 units)
#define XSS  136             // x_s row stride (floats)

typedef unsigned long long u64;

__device__ __forceinline__ unsigned f2tf32(float f) {
    unsigned u;
    asm("cvt.rna.tf32.f32 %0, %1;" : "=r"(u) : "f"(f));
    return u;
}
__device__ __forceinline__ void mma_tf32(float c[4],
    unsigned a0, unsigned a1, unsigned a2, unsigned a3,
    unsigned b0, unsigned b1)
{
    asm volatile(
        "mma.sync.aligned.m16n8k8.row.col.f32.tf32.tf32.f32 "
        "{%0,%1,%2,%3}, {%4,%5,%6,%7}, {%8,%9}, {%0,%1,%2,%3};"
        : "+f"(c[0]), "+f"(c[1]), "+f"(c[2]), "+f"(c[3])
        : "r"(a0), "r"(a1), "r"(a2), "r"(a3), "r"(b0), "r"(b1));
}

// ---- device scratch (prep-written paired-fragment layouts) ----
// g_Whg2[kk][n] = { w[k8*8+t][n], w[k8*8+t+4][n] }, kk = k8*4+t, n = 2i+mat
__device__ __align__(16) float g_Whg2[64 * NW2 * 2];
// g_Wff2[kk][d] = { wff[k*8+t][d], wff[k*8+t+4][d] }, kk = k*4+t (rows i>=170 zero)
__device__ __align__(16) float g_Wff2[88 * D_ * 2];
__device__ float g_partial[NBLK];
__device__ unsigned int g_ticket;

// ------------------------------------------------------------------
// Prep: 176 blocks x 96 threads.
// ------------------------------------------------------------------
__global__ __launch_bounds__(96) void prep_kernel(
    const float* __restrict__ Wh, const float* __restrict__ Wg,
    const float* __restrict__ Wff,
    const float* __restrict__ hs, const float* __restrict__ gs)
{
    int r    = blockIdx.x;               // 0..175
    int mat  = threadIdx.x >> 5;
    int lane = threadIdx.x & 31;

    if (mat < 2) {
        int n = 2 * r + mat;
        if (r < DI_) {
            const float4* W = (const float4*)(mat ? Wg : Wh);
            float4 v = W[r * 32 + lane];
            float ss = v.x * v.x + v.y * v.y + v.z * v.z + v.w * v.w;
            #pragma unroll
            for (int o = 16; o; o >>= 1) ss += __shfl_xor_sync(0xffffffffu, ss, o);
            float sc = rsqrtf(ss) * (mat ? gs[r] * SQRTD : hs[r]);
            float vv[4] = {v.x * sc, v.y * sc, v.z * sc, v.w * sc};
            #pragma unroll
            for (int k = 0; k < 4; k++) {
                int d = lane * 4 + k;
                int kk = (d >> 3) * 4 + (d & 3);
                int half = (d >> 2) & 1;
                g_Whg2[(kk * NW2 + n) * 2 + half] =
                    __uint_as_float(f2tf32(vv[k]));
            }
        } else if (r < 174) {            // zero pad cols 340..347
            #pragma unroll
            for (int k = 0; k < 4; k++) {
                int d = lane * 4 + k;
                int kk = (d >> 3) * 4 + (d & 3);
                int half = (d >> 2) & 1;
                g_Whg2[(kk * NW2 + n) * 2 + half] = 0.f;
            }
        }
    } else {
        float v[4] = {0.f, 0.f, 0.f, 0.f};
        if (r < DI_) {
            float ss = 0.f;
            #pragma unroll
            for (int k = 0; k < 4; k++) {
                v[k] = Wff[(lane + 32 * k) * DI_ + r];
                ss += v[k] * v[k];
            }
            #pragma unroll
            for (int o = 16; o; o >>= 1) ss += __shfl_xor_sync(0xffffffffu, ss, o);
            float inv = rsqrtf(ss);
            #pragma unroll
            for (int k = 0; k < 4; k++)
                v[k] = __uint_as_float(f2tf32(v[k] * inv));
        }
        int kk = (r >> 3) * 4 + (r & 3);
        int half = (r >> 2) & 1;
        #pragma unroll
        for (int k = 0; k < 4; k++)
            g_Wff2[((kk * D_) + lane + 32 * k) * 2 + half] = v[k];
    }
}

// ------------------------------------------------------------------
// Main: 128 blocks x 1024 threads, 32 batch rows/block.
// Paired-fragment mma (LDS.64 operands), phase-3 B direct from gmem.
//
// smem layout (bytes):
//   [0, 178176)       whg2 float2[64][348]
//   [178176, 196608)  emb2 float2[64][36]  / x_s float[32][136] after ph2
//   [196608, 221952)  a_t2 float2[88][36]
//   [221952, 222080)  wacc float[32]
//   [222080, 222084)  flag
// ------------------------------------------------------------------
#define OFF_EMB  178176
#define OFF_AT   196608
#define OFF_WACC 221952
#define OFF_FLAG 222080
#define SMEM_BYTES 222208

__global__ void __launch_bounds__(THREADS) main_kernel(
    const int*   __restrict__ input_ids,
    const int*   __restrict__ target_ids,
    const int*   __restrict__ neg_ids,
    const float* __restrict__ W_in,
    const float* __restrict__ W_out,
    const float* __restrict__ logit_scale,
    float*       __restrict__ out)
{
    extern __shared__ __align__(16) char smem[];
    const float2* whg2 = (const float2*)smem;
    float*  emb_f = (float*)(smem + OFF_EMB);
    const float2* emb2 = (const float2*)(smem + OFF_EMB);
    float*  x_s   = (float*)(smem + OFF_EMB);        // alias after phase 2
    float*  at_f  = (float*)(smem + OFF_AT);
    const float2* at2 = (const float2*)(smem + OFF_AT);
    float*  wacc  = (float*)(smem + OFF_WACC);
    int*    sflag = (int*)(smem + OFF_FLAG);

    const int tid  = threadIdx.x;
    const int lane = tid & 31;
    const int warp = tid >> 5;
    const int b0   = blockIdx.x * BT_;

    // ---- Async bulk copy whg2 (LDGSTS; wait before phase 2) ----
    {
        unsigned int sbase = (unsigned int)__cvta_generic_to_shared(smem);
        const float4* src = (const float4*)g_Whg2;
        #pragma unroll 1
        for (int f = tid; f < (64 * NW2 * 2) / 4; f += THREADS) {
            asm volatile("cp.async.cg.shared.global [%0], [%1], 16;"
                         :: "r"(sbase + f * 16), "l"(src + f));
        }
        asm volatile("cp.async.commit_group;");
    }

    // ---- Phase 1: gather + normalize + tf32 + paired-layout store ----
    {
        int row = input_ids[b0 + warp];
        float4 v = ((const float4*)(W_in + (size_t)row * D_))[lane];
        float ss = v.x * v.x + v.y * v.y + v.z * v.z + v.w * v.w;
        #pragma unroll
        for (int o = 16; o; o >>= 1) ss += __shfl_xor_sync(0xffffffffu, ss, o);
        float inv = rsqrtf(ss);
        float vv[4] = {v.x * inv, v.y * inv, v.z * inv, v.w * inv};
        #pragma unroll
        for (int k = 0; k < 4; k++) {
            int d = lane * 4 + k;
            int kk = (d >> 3) * 4 + (d & 3);
            int half = (d >> 2) & 1;
            emb_f[(kk * ES2 + warp) * 2 + half] =
                __uint_as_float(f2tf32(vv[k]));
        }
    }

    // ---- Prefetch phase-4 gather lines into L2 ----
    {
        int gb = b0 + warp;
        if (lane < 24) {
            int j = lane >> 2;
            int row = (j == 0) ? target_ids[gb] : neg_ids[gb * NEG_ + j - 1];
            const float* p = W_out + (size_t)row * D_ + (lane & 3) * 32;
            asm volatile("prefetch.global.L2 [%0];" :: "l"(p));
        } else if (lane < 30) {
            int j = lane - 24;
            int row = (j == 0) ? target_ids[gb] : neg_ids[gb * NEG_ + j - 1];
            const float* p = logit_scale + row;
            asm volatile("prefetch.global.L2 [%0];" :: "l"(p));
        }
    }
    asm volatile("cp.async.wait_group 0;");
    __syncthreads();

    // ================= Phase 2: [32x344] = emb @ whg via mma =================
    {
        int m  = warp & 1;
        int ns = warp >> 1;
        int g  = lane >> 2, t = lane & 3;
        float c0[4] = {0.f,0.f,0.f,0.f};
        float c1[4] = {0.f,0.f,0.f,0.f};
        float c2[4] = {0.f,0.f,0.f,0.f};
        const bool has3 = (ns < 11);
        #pragma unroll 4
        for (int k8 = 0; k8 < 16; k8++) {
            int kk = k8 * 4 + t;
            float2 a02 = emb2[kk * ES2 + m * 16 + g];      // {a0, a2}
            float2 a13 = emb2[kk * ES2 + m * 16 + g + 8];  // {a1, a3}
            unsigned a0 = __float_as_uint(a02.x), a1 = __float_as_uint(a13.x);
            unsigned a2 = __float_as_uint(a02.y), a3 = __float_as_uint(a13.y);
            float2 bb0 = whg2[kk * NW2 + ns * 8 + g];
            mma_tf32(c0, a0, a1, a2, a3,
                     __float_as_uint(bb0.x), __float_as_uint(bb0.y));
            float2 bb1 = whg2[kk * NW2 + ns * 8 + g + 128];
            mma_tf32(c1, a0, a1, a2, a3,
                     __float_as_uint(bb1.x), __float_as_uint(bb1.y));
            if (has3) {
                float2 bb2 = whg2[kk * NW2 + ns * 8 + g + 256];
                mma_tf32(c2, a0, a1, a2, a3,
                         __float_as_uint(bb2.x), __float_as_uint(bb2.y));
            }
        }
        // epilogue: c = [h(i), g(i)]; a = h*silu(g) -> a_t2 paired layout
        int bb = m * 16 + g;
        #pragma unroll
        for (int q = 0; q < 3; q++) {
            if (q == 2 && !has3) break;
            float* c = (q == 0) ? c0 : (q == 1) ? c1 : c2;
            int i = (ns + 16 * q) * 4 + t;
            int kk = (i >> 3) * 4 + (i & 3);
            int half = (i >> 2) & 1;
            float v0 = c[0] * (c[1] / (1.f + __expf(-c[1])));
            float v1 = c[2] * (c[3] / (1.f + __expf(-c[3])));
            at_f[(kk * ES2 + bb) * 2 + half]     = __uint_as_float(f2tf32(v0));
            at_f[(kk * ES2 + bb + 8) * 2 + half] = __uint_as_float(f2tf32(v1));
        }
    }
    // zero a_t2 slots for i = 170..175 (disjoint from epilogue writes)
    if (tid < 192) {
        const int kkz[6] = {86, 87, 84, 85, 86, 87};
        const int hz[6]  = { 0,  0,  1,  1,  1,  1};
        int q = tid >> 5, b = tid & 31;
        at_f[(kkz[q] * ES2 + b) * 2 + hz[q]] = 0.f;
    }
    __syncthreads();

    // ================= Phase 3: [32x128] = a @ Wff via mma; B from gmem =======
    {
        int m  = warp & 1;
        int dt = warp >> 1;
        int g  = lane >> 2, t = lane & 3;
        float c[4] = {0.f,0.f,0.f,0.f};
        const float2* Bg = (const float2*)g_Wff2;
        #pragma unroll 11
        for (int k = 0; k < 22; k++) {
            int kk = k * 4 + t;
            float2 a02 = at2[kk * ES2 + m * 16 + g];
            float2 a13 = at2[kk * ES2 + m * 16 + g + 8];
            float2 bb = __ldg(Bg + kk * D_ + dt * 8 + g);
            mma_tf32(c,
                     __float_as_uint(a02.x), __float_as_uint(a13.x),
                     __float_as_uint(a02.y), __float_as_uint(a13.y),
                     __float_as_uint(bb.x),  __float_as_uint(bb.y));
        }
        *(float2*)(x_s + (m * 16 + g) * XSS + dt * 8 + 2 * t)     = make_float2(c[0], c[1]);
        *(float2*)(x_s + (m * 16 + g + 8) * XSS + dt * 8 + 2 * t) = make_float2(c[2], c[3]);
    }

    // ---- Phase-4 gathers (x-independent) ----
    float4 wv[6];
    float  lsc[6];
    {
        int gb = b0 + warp;
        int rows4[6];
        #pragma unroll
        for (int j = 0; j < 6; j++)
            rows4[j] = (j == 0) ? target_ids[gb] : neg_ids[gb * NEG_ + (j - 1)];
        #pragma unroll
        for (int j = 0; j < 6; j++)
            wv[j] = ((const float4*)(W_out + (size_t)rows4[j] * D_))[lane];
        #pragma unroll
        for (int j = 0; j < 6; j++) lsc[j] = logit_scale[rows4[j]];
    }
    __syncthreads();

    // ---- Phase 4: 6 logits per row; warp = 1 batch row ----
    float local = 0.f;
    {
        float4 x4 = ((const float4*)(x_s + warp * XSS))[lane];
        #pragma unroll
        for (int j = 0; j < 6; j++) {
            float dot = wv[j].x * x4.x + wv[j].y * x4.y + wv[j].z * x4.z + wv[j].w * x4.w;
            float ss  = wv[j].x * wv[j].x + wv[j].y * wv[j].y + wv[j].z * wv[j].z + wv[j].w * wv[j].w;
            #pragma unroll
            for (int o = 16; o; o >>= 1) {
                dot += __shfl_xor_sync(0xffffffffu, dot, o);
                ss  += __shfl_xor_sync(0xffffffffu, ss, o);
            }
            if (lane == 0) {
                float logit = dot * rsqrtf(ss) * lsc[j] * SQRTD;
                float z = (j == 0) ? logit : -logit;
                float ls = fminf(z, 0.f) - log1pf(__expf(-fabsf(z)));
                local += ls * ((j == 0) ? (1.f / B_) : (1.f / (B_ * NEG_)));
            }
        }
    }
    if (lane == 0) wacc[warp] = local;
    __syncthreads();

    // ---- block partial + fused deterministic final reduction ----
    if (tid == 0) {
        float s = 0.f;
        #pragma unroll
        for (int w = 0; w < 32; w++) s += wacc[w];
        g_partial[blockIdx.x] = s;
        __threadfence();
        unsigned int t = atomicAdd(&g_ticket, 1u);
        sflag[0] = (t == NBLK - 1) ? 1 : 0;
    }
    __syncthreads();
    if (sflag[0]) {
        __threadfence();
        float* red = at_f;  // reuse smem
        if (tid < NBLK) red[tid] = g_partial[tid];
        __syncthreads();
        #pragma unroll
        for (int o = NBLK / 2; o; o >>= 1) {
            if (tid < o) red[tid] += red[tid + o];
            __syncthreads();
        }
        if (tid == 0) {
            out[0] = -red[0];
            g_ticket = 0;   // reset for next graph replay
        }
    }
}

extern "C" void kernel_launch(void* const* d_in, const int* in_sizes, int n_in,
                              void* d_out, int out_size)
{
    const int*   input_ids   = (const int*)  d_in[0];
    const int*   target_ids  = (const int*)  d_in[1];
    const int*   neg_ids     = (const int*)  d_in[2];
    const float* W_in        = (const float*)d_in[3];
    const float* W_out       = (const float*)d_in[4];
    const float* W_hidden    = (const float*)d_in[5];
    const float* W_gate      = (const float*)d_in[6];
    const float* W_ff_out    = (const float*)d_in[7];
    const float* hidden_sc   = (const float*)d_in[8];
    const float* gate_sc     = (const float*)d_in[9];
    const float* logit_scale = (const float*)d_in[10];
    float* out = (float*)d_out;

    cudaFuncSetAttribute(main_kernel, cudaFuncAttributeMaxDynamicSharedMemorySize, SMEM_BYTES);

    prep_kernel<<<DIP_, 96>>>(W_hidden, W_gate, W_ff_out, hidden_sc, gate_sc);
    main_kernel<<<NBLK, THREADS, SMEM_BYTES>>>(input_ids, target_ids, neg_ids,
                                               W_in, W_out, logit_scale, out);
}

// round 16
// speedup vs baseline: 1.2595x; 1.2595x over previous
#include <cuda_runtime.h>
#include <cuda_bf16.h>
#include <math.h>

#define V_   100000
#define D_   128
#define B_   4096
#define NEG_ 5
#define DI_  170
#define BT_  32
#define NBLK (B_ / BT_)      // 128
#define THREADS 1024
#define SQRTD 11.3137084989847604f

#define EMBW 68              // emb_s row stride (u32 words)
#define ATW  92              // a_t row stride (u32 words)
#define XSS  136             // x_s row stride (floats)

// ---- device scratch: fragment-linear bf16 weight arrays (prep-written) ----
// whgF[((ks*43 + tile)*32 + lane)*2 + reg] : B-frags for phase 2 (k16, n=2i+mat)
__device__ __align__(16) unsigned g_WhgF[8 * 43 * 32 * 2];
// wffF[((ks*16 + tile)*32 + lane)*2 + reg] : B-frags for phase 3 (k16=i, n=d)
__device__ __align__(16) unsigned g_WffF[11 * 16 * 32 * 2];
__device__ float g_partial[NBLK];
__device__ unsigned int g_ticket;

__device__ __forceinline__ void mma_bf16(float c[4],
    unsigned a0, unsigned a1, unsigned a2, unsigned a3,
    unsigned b0, unsigned b1)
{
    asm volatile(
        "mma.sync.aligned.m16n8k16.row.col.f32.bf16.bf16.f32 "
        "{%0,%1,%2,%3}, {%4,%5,%6,%7}, {%8,%9}, {%0,%1,%2,%3};"
        : "+f"(c[0]), "+f"(c[1]), "+f"(c[2]), "+f"(c[3])
        : "r"(a0), "r"(a1), "r"(a2), "r"(a3), "r"(b0), "r"(b1));
}
__device__ __forceinline__ unsigned pk_bf16(float lo, float hi) {
    unsigned r;
    asm("cvt.rn.bf16x2.f32 %0, %1, %2;" : "=r"(r) : "f"(hi), "f"(lo));
    return r;
}

// ------------------------------------------------------------------
// Prep: 176 blocks x 96 threads. Writes bf16 fragment-linear layouts.
//  warp0/1 (mat): Wh/Wg row r -> frag slots for n = 2r+mat (r<172)
//  warp2: Wff column r -> frag slots for k-row i=r (zeros for r>=170)
// ------------------------------------------------------------------
__global__ __launch_bounds__(96) void prep_kernel(
    const float* __restrict__ Wh, const float* __restrict__ Wg,
    const float* __restrict__ Wff,
    const float* __restrict__ hs, const float* __restrict__ gs)
{
    int r    = blockIdx.x;               // 0..175
    int mat  = threadIdx.x >> 5;
    int lane = threadIdx.x & 31;

    if (mat < 2) {
        if (r >= 172) return;            // n = 2r+mat covers 0..343
        int n = 2 * r + mat;
        float vv[4] = {0.f, 0.f, 0.f, 0.f};
        if (r < DI_) {
            const float4* W = (const float4*)(mat ? Wg : Wh);
            float4 v = W[r * 32 + lane];
            float ss = v.x * v.x + v.y * v.y + v.z * v.z + v.w * v.w;
            #pragma unroll
            for (int o = 16; o; o >>= 1) ss += __shfl_xor_sync(0xffffffffu, ss, o);
            float sc = rsqrtf(ss) * (mat ? gs[r] * SQRTD : hs[r]);
            vv[0] = v.x * sc; vv[1] = v.y * sc; vv[2] = v.z * sc; vv[3] = v.w * sc;
        }
        int g = n & 7, tile = n >> 3;
        #pragma unroll
        for (int k = 0; k < 4; k++) {
            int d   = lane * 4 + k;      // k-dim index (0..127)
            int ks  = d >> 4;
            int rem = d & 15;
            int reg = rem >> 3;
            int t   = (rem & 7) >> 1;
            int hi  = rem & 1;
            ((__nv_bfloat16*)g_WhgF)[((((ks * 43 + tile) * 32) + g * 4 + t) * 2 + reg) * 2 + hi] =
                __float2bfloat16(vv[k]);
        }
    } else {
        float v[4] = {0.f, 0.f, 0.f, 0.f};
        if (r < DI_) {
            float ss = 0.f;
            #pragma unroll
            for (int k = 0; k < 4; k++) {
                v[k] = Wff[(lane + 32 * k) * DI_ + r];
                ss += v[k] * v[k];
            }
            #pragma unroll
            for (int o = 16; o; o >>= 1) ss += __shfl_xor_sync(0xffffffffu, ss, o);
            float inv = rsqrtf(ss);
            #pragma unroll
            for (int k = 0; k < 4; k++) v[k] *= inv;
        }
        int ks  = r >> 4;                // k-dim index is i = r (0..175)
        int rem = r & 15;
        int reg = rem >> 3;
        int t   = (rem & 7) >> 1;
        int hi  = rem & 1;
        #pragma unroll
        for (int k = 0; k < 4; k++) {
            int d = lane + 32 * k;       // n-dim index (0..127)
            int g = d & 7, tile = d >> 3;
            ((__nv_bfloat16*)g_WffF)[((((ks * 16 + tile) * 32) + g * 4 + t) * 2 + reg) * 2 + hi] =
                __float2bfloat16(v[k]);
        }
    }
}

// ------------------------------------------------------------------
// Main: 128 blocks x 1024 threads, 32 batch rows/block.
// bf16 m16n8k16 mma, fragment-linear B, both weights cp.async'd at start.
//
// smem layout (bytes):
//   [0, 88064)        whgF  u32[22016]  (phase-2 B frags)
//   [88064, 133120)   wffF  u32[11264]  (phase-3 B frags)
//   [133120, 141824)  emb_s u32[32][68] (bf16x2 words, d-pairs)
//   [141824, 153600)  a_t   u32[32][92] (bf16x2 words, i-pairs)
//   [153600, 171008)  x_s   float[32][136]
//   [171008, 171136)  wacc  float[32]
//   [171136, 171140)  flag
// ------------------------------------------------------------------
#define OFF_WFF  88064
#define OFF_EMB  133120
#define OFF_AT   141824
#define OFF_XS   153600
#define OFF_WACC 171008
#define OFF_FLAG 171136
#define SMEM_BYTES 171264

__global__ void __launch_bounds__(THREADS) main_kernel(
    const int*   __restrict__ input_ids,
    const int*   __restrict__ target_ids,
    const int*   __restrict__ neg_ids,
    const float* __restrict__ W_in,
    const float* __restrict__ W_out,
    const float* __restrict__ logit_scale,
    float*       __restrict__ out)
{
    extern __shared__ __align__(16) char smem[];
    const uint2*    whgF  = (const uint2*)smem;
    const uint2*    wffF  = (const uint2*)(smem + OFF_WFF);
    unsigned*       emb_u = (unsigned*)(smem + OFF_EMB);
    unsigned*       at_u  = (unsigned*)(smem + OFF_AT);
    __nv_bfloat16*  at_h  = (__nv_bfloat16*)(smem + OFF_AT);
    float*          x_s   = (float*)(smem + OFF_XS);
    float*          wacc  = (float*)(smem + OFF_WACC);
    int*            sflag = (int*)(smem + OFF_FLAG);

    const int tid  = threadIdx.x;
    const int lane = tid & 31;
    const int warp = tid >> 5;
    const int b0   = blockIdx.x * BT_;

    // ---- cp.async BOTH weight frag arrays at kernel start ----
    {
        unsigned int sbase = (unsigned int)__cvta_generic_to_shared(smem);
        const float4* s1 = (const float4*)g_WhgF;
        #pragma unroll 1
        for (int f = tid; f < 88064 / 16; f += THREADS)
            asm volatile("cp.async.cg.shared.global [%0], [%1], 16;"
                         :: "r"(sbase + f * 16), "l"(s1 + f));
        const float4* s2 = (const float4*)g_WffF;
        #pragma unroll 1
        for (int f = tid; f < 45056 / 16; f += THREADS)
            asm volatile("cp.async.cg.shared.global [%0], [%1], 16;"
                         :: "r"(sbase + OFF_WFF + f * 16), "l"(s2 + f));
        asm volatile("cp.async.commit_group;");
    }

    // ---- Phase 1: gather + l2-normalize + bf16-pack 32 embeddings ----
    {
        int row = input_ids[b0 + warp];
        float4 v = ((const float4*)(W_in + (size_t)row * D_))[lane];
        float ss = v.x * v.x + v.y * v.y + v.z * v.z + v.w * v.w;
        #pragma unroll
        for (int o = 16; o; o >>= 1) ss += __shfl_xor_sync(0xffffffffu, ss, o);
        float inv = rsqrtf(ss);
        unsigned w0 = pk_bf16(v.x * inv, v.y * inv);   // d = 4l, 4l+1
        unsigned w1 = pk_bf16(v.z * inv, v.w * inv);   // d = 4l+2, 4l+3
        *(uint2*)(emb_u + warp * EMBW + 2 * lane) = make_uint2(w0, w1);
    }

    // ---- Prefetch phase-4 gather lines into L2 ----
    {
        int gb = b0 + warp;
        if (lane < 24) {
            int j = lane >> 2;
            int row = (j == 0) ? target_ids[gb] : neg_ids[gb * NEG_ + j - 1];
            const float* p = W_out + (size_t)row * D_ + (lane & 3) * 32;
            asm volatile("prefetch.global.L2 [%0];" :: "l"(p));
        } else if (lane < 30) {
            int j = lane - 24;
            int row = (j == 0) ? target_ids[gb] : neg_ids[gb * NEG_ + j - 1];
            const float* p = logit_scale + row;
            asm volatile("prefetch.global.L2 [%0];" :: "l"(p));
        }
    }
    asm volatile("cp.async.wait_group 0;");
    __syncthreads();

    // ============ Phase 2: [32 x 344] = emb @ whg, bf16 k16 mma ============
    {
        int m  = warp & 1;
        int ns = warp >> 1;
        int g  = lane >> 2, t = lane & 3;
        float c0[4] = {0.f,0.f,0.f,0.f};
        float c1[4] = {0.f,0.f,0.f,0.f};
        float c2[4] = {0.f,0.f,0.f,0.f};
        const bool has3 = (ns < 11);
        const unsigned* E0 = emb_u + (m * 16 + g) * EMBW + t;
        const unsigned* E1 = emb_u + (m * 16 + g + 8) * EMBW + t;
        #pragma unroll
        for (int ks = 0; ks < 8; ks++) {
            unsigned a0 = E0[ks * 8];
            unsigned a1 = E1[ks * 8];
            unsigned a2 = E0[ks * 8 + 4];
            unsigned a3 = E1[ks * 8 + 4];
            uint2 b = whgF[(ks * 43 + ns) * 32 + lane];
            mma_bf16(c0, a0, a1, a2, a3, b.x, b.y);
            b = whgF[(ks * 43 + ns + 16) * 32 + lane];
            mma_bf16(c1, a0, a1, a2, a3, b.x, b.y);
            if (has3) {
                b = whgF[(ks * 43 + ns + 32) * 32 + lane];
                mma_bf16(c2, a0, a1, a2, a3, b.x, b.y);
            }
        }
        // epilogue: c = [h(i), g(i)] at n = tile*8 + 2t(+1); a = h*silu(g)
        int r0 = (m * 16 + g) * (2 * ATW);          // bf16 row offset
        int r1 = (m * 16 + g + 8) * (2 * ATW);
        #pragma unroll
        for (int q = 0; q < 3; q++) {
            if (q == 2 && !has3) break;
            float* c = (q == 0) ? c0 : (q == 1) ? c1 : c2;
            int i = (ns + 16 * q) * 4 + t;
            float v0 = c[0] * (c[1] / (1.f + __expf(-c[1])));
            float v1 = c[2] * (c[3] / (1.f + __expf(-c[3])));
            at_h[r0 + i] = __float2bfloat16(v0);
            at_h[r1 + i] = __float2bfloat16(v1);
        }
    }
    // zero a_t words 88..91 pad + i=172..175 (words 86,87) for all rows
    if (tid < 192) {
        int row = tid / 6, w = 86 + (tid % 6);
        at_u[row * ATW + w] = 0;
    }
    __syncthreads();

    // ============ Phase 3: [32 x 128] = a @ wff, bf16 k16 mma ============
    {
        int m  = warp & 1;
        int dt = warp >> 1;
        int g  = lane >> 2, t = lane & 3;
        float c[4] = {0.f,0.f,0.f,0.f};
        const unsigned* A0 = at_u + (m * 16 + g) * ATW + t;
        const unsigned* A1 = at_u + (m * 16 + g + 8) * ATW + t;
        #pragma unroll
        for (int ks = 0; ks < 11; ks++) {
            unsigned a0 = A0[ks * 8];
            unsigned a1 = A1[ks * 8];
            unsigned a2 = A0[ks * 8 + 4];
            unsigned a3 = A1[ks * 8 + 4];
            uint2 b = wffF[(ks * 16 + dt) * 32 + lane];
            mma_bf16(c, a0, a1, a2, a3, b.x, b.y);
        }
        *(float2*)(x_s + (m * 16 + g) * XSS + dt * 8 + 2 * t)     = make_float2(c[0], c[1]);
        *(float2*)(x_s + (m * 16 + g + 8) * XSS + dt * 8 + 2 * t) = make_float2(c[2], c[3]);
    }

    // ---- Phase-4 gathers (x-independent) ----
    float4 wv[6];
    float  lsc[6];
    {
        int gb = b0 + warp;
        int rows4[6];
        #pragma unroll
        for (int j = 0; j < 6; j++)
            rows4[j] = (j == 0) ? target_ids[gb] : neg_ids[gb * NEG_ + (j - 1)];
        #pragma unroll
        for (int j = 0; j < 6; j++)
            wv[j] = ((const float4*)(W_out + (size_t)rows4[j] * D_))[lane];
        #pragma unroll
        for (int j = 0; j < 6; j++) lsc[j] = logit_scale[rows4[j]];
    }
    __syncthreads();

    // ---- Phase 4: 6 logits per row; warp = 1 batch row ----
    float local = 0.f;
    {
        float4 x4 = ((const float4*)(x_s + warp * XSS))[lane];
        #pragma unroll
        for (int j = 0; j < 6; j++) {
            float dot = wv[j].x * x4.x + wv[j].y * x4.y + wv[j].z * x4.z + wv[j].w * x4.w;
            float ss  = wv[j].x * wv[j].x + wv[j].y * wv[j].y + wv[j].z * wv[j].z + wv[j].w * wv[j].w;
            #pragma unroll
            for (int o = 16; o; o >>= 1) {
                dot += __shfl_xor_sync(0xffffffffu, dot, o);
                ss  += __shfl_xor_sync(0xffffffffu, ss, o);
            }
            if (lane == 0) {
                float logit = dot * rsqrtf(ss) * lsc[j] * SQRTD;
                float z = (j == 0) ? logit : -logit;
                float ls = fminf(z, 0.f) - log1pf(__expf(-fabsf(z)));
                local += ls * ((j == 0) ? (1.f / B_) : (1.f / (B_ * NEG_)));
            }
        }
    }
    if (lane == 0) wacc[warp] = local;
    __syncthreads();

    // ---- block partial + fused deterministic final reduction ----
    if (tid == 0) {
        float s = 0.f;
        #pragma unroll
        for (int w = 0; w < 32; w++) s += wacc[w];
        g_partial[blockIdx.x] = s;
        __threadfence();
        unsigned int t = atomicAdd(&g_ticket, 1u);
        sflag[0] = (t == NBLK - 1) ? 1 : 0;
    }
    __syncthreads();
    if (sflag[0]) {
        __threadfence();
        float* red = (float*)at_u;   // reuse smem as fp32 scratch
        if (tid < NBLK) red[tid] = g_partial[tid];
        __syncthreads();
        #pragma unroll
        for (int o = NBLK / 2; o; o >>= 1) {
            if (tid < o) red[tid] += red[tid + o];
            __syncthreads();
        }
        if (tid == 0) {
            out[0] = -red[0];
            g_ticket = 0;            // reset for next graph replay
        }
    }
}

extern "C" void kernel_launch(void* const* d_in, const int* in_sizes, int n_in,
                              void* d_out, int out_size)
{
    const int*   input_ids   = (const int*)  d_in[0];
    const int*   target_ids  = (const int*)  d_in[1];
    const int*   neg_ids     = (const int*)  d_in[2];
    const float* W_in        = (const float*)d_in[3];
    const float* W_out       = (const float*)d_in[4];
    const float* W_hidden    = (const float*)d_in[5];
    const float* W_gate      = (const float*)d_in[6];
    const float* W_ff_out    = (const float*)d_in[7];
    const float* hidden_sc   = (const float*)d_in[8];
    const float* gate_sc     = (const float*)d_in[9];
    const float* logit_scale = (const float*)d_in[10];
    float* out = (float*)d_out;

    cudaFuncSetAttribute(main_kernel, cudaFuncAttributeMaxDynamicSharedMemorySize, SMEM_BYTES);

    prep_kernel<<<176, 96>>>(W_hidden, W_gate, W_ff_out, hidden_sc, gate_sc);
    main_kernel<<<NBLK, THREADS, SMEM_BYTES>>>(input_ids, target_ids, neg_ids,
                                               W_in, W_out, logit_scale, out);
}

// round 17
// speedup vs baseline: 1.3788x; 1.0947x over previous
#include <cuda_runtime.h>
#include <cuda_bf16.h>
#include <math.h>

#define V_   100000
#define D_   128
#define B_   4096
#define NEG_ 5
#define DI_  170
#define BT_  32
#define NBLK 128
#define THREADS 1024
#define SQRTD 11.3137084989847604f

#define EMBW 68              // emb_s row stride (u32 words)
#define ATW  92              // a_t row stride (u32 words)
#define XSS  136             // x_s row stride (floats)

// ---- device scratch: fragment-linear bf16 weight arrays (written in-kernel) ----
__device__ __align__(16) unsigned g_WhgF[8 * 43 * 32 * 2];   // phase-2 B frags
__device__ __align__(16) unsigned g_WffF[11 * 16 * 32 * 2];  // phase-3 B frags
__device__ float g_partial[NBLK];
__device__ unsigned g_ticket;
__device__ unsigned g_prep_done;

__device__ __forceinline__ void mma_bf16(float c[4],
    unsigned a0, unsigned a1, unsigned a2, unsigned a3,
    unsigned b0, unsigned b1)
{
    asm volatile(
        "mma.sync.aligned.m16n8k16.row.col.f32.bf16.bf16.f32 "
        "{%0,%1,%2,%3}, {%4,%5,%6,%7}, {%8,%9}, {%0,%1,%2,%3};"
        : "+f"(c[0]), "+f"(c[1]), "+f"(c[2]), "+f"(c[3])
        : "r"(a0), "r"(a1), "r"(a2), "r"(a3), "r"(b0), "r"(b1));
}
__device__ __forceinline__ unsigned pk_bf16(float lo, float hi) {
    unsigned r;
    asm("cvt.rn.bf16x2.f32 %0, %1, %2;" : "=r"(r) : "f"(hi), "f"(lo));
    return r;
}

// ------------------------------------------------------------------
// Single fused kernel: 128 blocks x 1024 threads (single wave on 148 SMs).
// Distributed prep (520 warp-tasks) + gmem spin barrier, then mma phases
// with B-fragments read directly from gmem (L2-hot).
//
// smem layout (bytes):
//   [0, 8704)       emb_s u32[32][68] (bf16x2 words, d-pairs)
//   [8704, 20480)   a_t   u32[32][92] (bf16x2 words, i-pairs)
//   [20480, 37888)  x_s   float[32][136]
//   [37888, 38016)  wacc  float[32]
//   [38016, 38020)  flag
// ------------------------------------------------------------------
#define OFF_AT   8704
#define OFF_XS   20480
#define OFF_WACC 37888
#define OFF_FLAG 38016
#define SMEM_BYTES 38144

__global__ void __launch_bounds__(THREADS) main_kernel(
    const int*   __restrict__ input_ids,
    const int*   __restrict__ target_ids,
    const int*   __restrict__ neg_ids,
    const float* __restrict__ W_in,
    const float* __restrict__ W_out,
    const float* __restrict__ Wh,
    const float* __restrict__ Wg,
    const float* __restrict__ Wff,
    const float* __restrict__ hs,
    const float* __restrict__ gs,
    const float* __restrict__ logit_scale,
    float*       __restrict__ out)
{
    extern __shared__ __align__(16) char smem[];
    unsigned*       emb_u = (unsigned*)smem;
    unsigned*       at_u  = (unsigned*)(smem + OFF_AT);
    __nv_bfloat16*  at_h  = (__nv_bfloat16*)(smem + OFF_AT);
    float*          x_s   = (float*)(smem + OFF_XS);
    float*          wacc  = (float*)(smem + OFF_WACC);
    int*            sflag = (int*)(smem + OFF_FLAG);

    const int tid  = threadIdx.x;
    const int lane = tid & 31;
    const int warp = tid >> 5;
    const int b0   = blockIdx.x * BT_;

    // ---- Distributed prep: task t = warp*128 + blockIdx.x (520 tasks) ----
    if (warp <= 4) {
        int t = warp * NBLK + blockIdx.x;
        if (t < 520) {
            if (t < 344) {
                // whg task: normalize Wh/Wg row r, write phase-2 frag slots
                int mat = t & 1, r = t >> 1;        // r 0..171
                float vv[4] = {0.f, 0.f, 0.f, 0.f};
                if (r < DI_) {
                    const float4* W = (const float4*)(mat ? Wg : Wh);
                    float4 v = W[r * 32 + lane];
                    float ss = v.x * v.x + v.y * v.y + v.z * v.z + v.w * v.w;
                    #pragma unroll
                    for (int o = 16; o; o >>= 1) ss += __shfl_xor_sync(0xffffffffu, ss, o);
                    float sc = rsqrtf(ss) * (mat ? gs[r] * SQRTD : hs[r]);
                    vv[0] = v.x * sc; vv[1] = v.y * sc; vv[2] = v.z * sc; vv[3] = v.w * sc;
                }
                int n = 2 * r + mat;
                int g = n & 7, tile = n >> 3;
                #pragma unroll
                for (int k = 0; k < 4; k++) {
                    int d   = lane * 4 + k;          // k-dim (0..127)
                    int ks  = d >> 4;
                    int rem = d & 15;
                    int reg = rem >> 3;
                    int tt  = (rem & 7) >> 1;
                    int hi  = rem & 1;
                    ((__nv_bfloat16*)g_WhgF)[((((ks * 43 + tile) * 32) + g * 4 + tt) * 2 + reg) * 2 + hi] =
                        __float2bfloat16(vv[k]);
                }
            } else {
                // wff task: normalize Wff column r, write phase-3 frag slots
                int r = t - 344;                     // 0..175
                float v[4] = {0.f, 0.f, 0.f, 0.f};
                if (r < DI_) {
                    float ss = 0.f;
                    #pragma unroll
                    for (int k = 0; k < 4; k++) {
                        v[k] = Wff[(lane + 32 * k) * DI_ + r];
                        ss += v[k] * v[k];
                    }
                    #pragma unroll
                    for (int o = 16; o; o >>= 1) ss += __shfl_xor_sync(0xffffffffu, ss, o);
                    float inv = rsqrtf(ss);
                    #pragma unroll
                    for (int k = 0; k < 4; k++) v[k] *= inv;
                }
                int ks  = r >> 4;
                int rem = r & 15;
                int reg = rem >> 3;
                int tt  = (rem & 7) >> 1;
                int hi  = rem & 1;
                #pragma unroll
                for (int k = 0; k < 4; k++) {
                    int d = lane + 32 * k;           // n-dim (0..127)
                    int g = d & 7, tile = d >> 3;
                    ((__nv_bfloat16*)g_WffF)[((((ks * 16 + tile) * 32) + g * 4 + tt) * 2 + reg) * 2 + hi] =
                        __float2bfloat16(v[k]);
                }
            }
        }
    }
    __syncthreads();
    if (tid == 0) {                                   // publish this block's prep
        __threadfence();
        atomicAdd(&g_prep_done, 1u);
    }

    // ---- Phase 1: gather + l2-normalize + bf16-pack 32 embeddings ----
    {
        int row = input_ids[b0 + warp];
        float4 v = ((const float4*)(W_in + (size_t)row * D_))[lane];
        float ss = v.x * v.x + v.y * v.y + v.z * v.z + v.w * v.w;
        #pragma unroll
        for (int o = 16; o; o >>= 1) ss += __shfl_xor_sync(0xffffffffu, ss, o);
        float inv = rsqrtf(ss);
        unsigned w0 = pk_bf16(v.x * inv, v.y * inv);
        unsigned w1 = pk_bf16(v.z * inv, v.w * inv);
        *(uint2*)(emb_u + warp * EMBW + 2 * lane) = make_uint2(w0, w1);
    }

    // ---- Prefetch phase-4 gather lines into L2 ----
    {
        int gb = b0 + warp;
        if (lane < 24) {
            int j = lane >> 2;
            int row = (j == 0) ? target_ids[gb] : neg_ids[gb * NEG_ + j - 1];
            const float* p = W_out + (size_t)row * D_ + (lane & 3) * 32;
            asm volatile("prefetch.global.L2 [%0];" :: "l"(p));
        } else if (lane < 30) {
            int j = lane - 24;
            int row = (j == 0) ? target_ids[gb] : neg_ids[gb * NEG_ + j - 1];
            const float* p = logit_scale + row;
            asm volatile("prefetch.global.L2 [%0];" :: "l"(p));
        }
    }

    // ---- Global spin barrier: all 128 blocks' prep visible ----
    __syncthreads();
    if (tid == 0) {
        while (*((volatile unsigned*)&g_prep_done) < (unsigned)NBLK) { }
    }
    __syncthreads();

    // ============ Phase 2: [32 x 344] = emb @ whg, bf16 k16 mma ============
    {
        int m  = warp & 1;
        int ns = warp >> 1;
        int g  = lane >> 2, t = lane & 3;
        float c0[4] = {0.f,0.f,0.f,0.f};
        float c1[4] = {0.f,0.f,0.f,0.f};
        float c2[4] = {0.f,0.f,0.f,0.f};
        const bool has3 = (ns < 11);
        const unsigned* E0 = emb_u + (m * 16 + g) * EMBW + t;
        const unsigned* E1 = emb_u + (m * 16 + g + 8) * EMBW + t;
        const uint2* BW = (const uint2*)g_WhgF;
        #pragma unroll
        for (int ks = 0; ks < 8; ks++) {
            unsigned a0 = E0[ks * 8];
            unsigned a1 = E1[ks * 8];
            unsigned a2 = E0[ks * 8 + 4];
            unsigned a3 = E1[ks * 8 + 4];
            uint2 b = __ldg(BW + (ks * 43 + ns) * 32 + lane);
            mma_bf16(c0, a0, a1, a2, a3, b.x, b.y);
            b = __ldg(BW + (ks * 43 + ns + 16) * 32 + lane);
            mma_bf16(c1, a0, a1, a2, a3, b.x, b.y);
            if (has3) {
                b = __ldg(BW + (ks * 43 + ns + 32) * 32 + lane);
                mma_bf16(c2, a0, a1, a2, a3, b.x, b.y);
            }
        }
        // epilogue: c = [h(i), g(i)]; a = h*silu(g) -> a_t bf16
        int r0 = (m * 16 + g) * (2 * ATW);
        int r1 = (m * 16 + g + 8) * (2 * ATW);
        #pragma unroll
        for (int q = 0; q < 3; q++) {
            if (q == 2 && !has3) break;
            float* c = (q == 0) ? c0 : (q == 1) ? c1 : c2;
            int i = (ns + 16 * q) * 4 + t;
            float v0 = c[0] * (c[1] / (1.f + __expf(-c[1])));
            float v1 = c[2] * (c[3] / (1.f + __expf(-c[3])));
            at_h[r0 + i] = __float2bfloat16(v0);
            at_h[r1 + i] = __float2bfloat16(v1);
        }
    }
    // zero a_t words 86..91 (i = 172..175 + pad) for all rows
    if (tid < 192) {
        int row = tid / 6, w = 86 + (tid % 6);
        at_u[row * ATW + w] = 0;
    }
    __syncthreads();

    // ============ Phase 3: [32 x 128] = a @ wff, bf16 k16 mma ============
    {
        int m  = warp & 1;
        int dt = warp >> 1;
        int g  = lane >> 2, t = lane & 3;
        float c[4] = {0.f,0.f,0.f,0.f};
        const unsigned* A0 = at_u + (m * 16 + g) * ATW + t;
        const unsigned* A1 = at_u + (m * 16 + g + 8) * ATW + t;
        const uint2* BF = (const uint2*)g_WffF;
        #pragma unroll
        for (int ks = 0; ks < 11; ks++) {
            unsigned a0 = A0[ks * 8];
            unsigned a1 = A1[ks * 8];
            unsigned a2 = A0[ks * 8 + 4];
            unsigned a3 = A1[ks * 8 + 4];
            uint2 b = __ldg(BF + (ks * 16 + dt) * 32 + lane);
            mma_bf16(c, a0, a1, a2, a3, b.x, b.y);
        }
        *(float2*)(x_s + (m * 16 + g) * XSS + dt * 8 + 2 * t)     = make_float2(c[0], c[1]);
        *(float2*)(x_s + (m * 16 + g + 8) * XSS + dt * 8 + 2 * t) = make_float2(c[2], c[3]);
    }

    // ---- Phase-4 gathers (x-independent; L2-hot from prefetch) ----
    float4 wv[6];
    float  lsc[6];
    {
        int gb = b0 + warp;
        int rows4[6];
        #pragma unroll
        for (int j = 0; j < 6; j++)
            rows4[j] = (j == 0) ? target_ids[gb] : neg_ids[gb * NEG_ + (j - 1)];
        #pragma unroll
        for (int j = 0; j < 6; j++)
            wv[j] = ((const float4*)(W_out + (size_t)rows4[j] * D_))[lane];
        #pragma unroll
        for (int j = 0; j < 6; j++) lsc[j] = logit_scale[rows4[j]];
    }
    __syncthreads();

    // ---- Phase 4: 6 logits per row; warp = 1 batch row ----
    float local = 0.f;
    {
        float4 x4 = ((const float4*)(x_s + warp * XSS))[lane];
        #pragma unroll
        for (int j = 0; j < 6; j++) {
            float dot = wv[j].x * x4.x + wv[j].y * x4.y + wv[j].z * x4.z + wv[j].w * x4.w;
            float ss  = wv[j].x * wv[j].x + wv[j].y * wv[j].y + wv[j].z * wv[j].z + wv[j].w * wv[j].w;
            #pragma unroll
            for (int o = 16; o; o >>= 1) {
                dot += __shfl_xor_sync(0xffffffffu, dot, o);
                ss  += __shfl_xor_sync(0xffffffffu, ss, o);
            }
            if (lane == 0) {
                float logit = dot * rsqrtf(ss) * lsc[j] * SQRTD;
                float z = (j == 0) ? logit : -logit;
                float ls = fminf(z, 0.f) - log1pf(__expf(-fabsf(z)));
                local += ls * ((j == 0) ? (1.f / B_) : (1.f / (B_ * NEG_)));
            }
        }
    }
    if (lane == 0) wacc[warp] = local;
    __syncthreads();

    // ---- block partial + fused deterministic final reduction ----
    if (tid == 0) {
        float s = 0.f;
        #pragma unroll
        for (int w = 0; w < 32; w++) s += wacc[w];
        g_partial[blockIdx.x] = s;
        __threadfence();
        unsigned int t = atomicAdd(&g_ticket, 1u);
        sflag[0] = (t == NBLK - 1) ? 1 : 0;
    }
    __syncthreads();
    if (sflag[0]) {
        __threadfence();
        float* red = (float*)at_u;   // reuse smem as fp32 scratch
        if (tid < NBLK) red[tid] = g_partial[tid];
        __syncthreads();
        #pragma unroll
        for (int o = NBLK / 2; o; o >>= 1) {
            if (tid < o) red[tid] += red[tid + o];
            __syncthreads();
        }
        if (tid == 0) {
            out[0] = -red[0];
            g_ticket = 0;            // reset for next graph replay
            g_prep_done = 0;
        }
    }
}

extern "C" void kernel_launch(void* const* d_in, const int* in_sizes, int n_in,
                              void* d_out, int out_size)
{
    const int*   input_ids   = (const int*)  d_in[0];
    const int*   target_ids  = (const int*)  d_in[1];
    const int*   neg_ids     = (const int*)  d_in[2];
    const float* W_in        = (const float*)d_in[3];
    const float* W_out       = (const float*)d_in[4];
    const float* W_hidden    = (const float*)d_in[5];
    const float* W_gate      = (const float*)d_in[6];
    const float* W_ff_out    = (const float*)d_in[7];
    const float* hidden_sc   = (const float*)d_in[8];
    const float* gate_sc     = (const float*)d_in[9];
    const float* logit_scale = (const float*)d_in[10];
    float* out = (float*)d_out;

    cudaFuncSetAttribute(main_kernel, cudaFuncAttributeMaxDynamicSharedMemorySize, SMEM_BYTES);

    main_kernel<<<NBLK, THREADS, SMEM_BYTES>>>(input_ids, target_ids, neg_ids,
                                               W_in, W_out, W_hidden, W_gate,
                                               W_ff_out, hidden_sc, gate_sc,
                                               logit_scale, out);
}